// round 6
// baseline (speedup 1.0000x reference)
#include <cuda_runtime.h>
#include <cstdint>

typedef unsigned long long ull;

#define CDIM 256
#define KCB  8192
#define NTOK 16384
#define OUT_ELEMS (16*256*32*32)

#define TOK_TILE 64
#define KHALF    4096
#define VQ_GRID  ((NTOK / TOK_TILE) * 2)   // 512
#define VQ_SMEM  (TOK_TILE * CDIM * 4)     // 64 KB

__device__ float g_en[KCB * CDIM];     // normalized codebook fp32 row-major
__device__ float g_corr[KCB];          // 0.5*|e_n|^2
__device__ ull   g_zt2[NTOK * 128];    // tokens packed f32x2: [blk64][c2][t]
__device__ ull   g_top[2][NTOK];       // per-K-half packed best
__device__ int   g_idx[NTOK];

// ---------------- helpers ----------------
__device__ __forceinline__ uint32_t smem_u32(const void* p) {
    uint32_t a;
    asm("{ .reg .u64 t; cvta.to.shared.u64 t, %1; cvt.u32.u64 %0, t; }" : "=r"(a) : "l"(p));
    return a;
}
#define CP16(dst, src) asm volatile("cp.async.cg.shared.global [%0], [%1], 16;" :: "r"(dst), "l"(src) : "memory")
#define CP_COMMIT()    asm volatile("cp.async.commit_group;" ::: "memory")
#define CP_WAIT0()     asm volatile("cp.async.wait_group 0;" ::: "memory")

__device__ __forceinline__ void ffma2(ull& d, ull a, ull b) {
    asm("fma.rn.f32x2 %0, %1, %2, %0;" : "+l"(d) : "l"(a), "l"(b));
}
__device__ __forceinline__ float pair_sum(ull v) {
    float lo, hi;
    asm("mov.b64 {%0,%1}, %2;" : "=f"(lo), "=f"(hi) : "l"(v));
    return lo + hi;
}
__device__ __forceinline__ unsigned fmap(float v) {
    unsigned u = __float_as_uint(v);
    return (u & 0x80000000u) ? ~u : (u | 0x80000000u);
}

// ---------------- preprocessing ----------------
__global__ void norm_codebook(const float* __restrict__ emb) {
    int row  = blockIdx.x * 8 + (threadIdx.x >> 5);
    int lane = threadIdx.x & 31;
    const float4* w = (const float4*)(emb + (size_t)row * CDIM);
    float4 a = __ldg(w + lane);
    float4 b = __ldg(w + lane + 32);
    float ss = a.x*a.x + a.y*a.y + a.z*a.z + a.w*a.w
             + b.x*b.x + b.y*b.y + b.z*b.z + b.w*b.w;
    #pragma unroll
    for (int s = 16; s; s >>= 1) ss += __shfl_xor_sync(0xffffffffu, ss, s);
    float inv = 1.0f / fmaxf(sqrtf(ss), 1e-12f);
    float v[8];
    v[0]=a.x*inv; v[1]=a.y*inv; v[2]=a.z*inv; v[3]=a.w*inv;
    v[4]=b.x*inv; v[5]=b.y*inv; v[6]=b.z*inv; v[7]=b.w*inv;
    float4* o = (float4*)(g_en + (size_t)row * CDIM);
    o[lane]      = make_float4(v[0], v[1], v[2], v[3]);
    o[lane + 32] = make_float4(v[4], v[5], v[6], v[7]);
    float ss2 = 0.f;
    #pragma unroll
    for (int j = 0; j < 8; j++) ss2 = fmaf(v[j], v[j], ss2);
    #pragma unroll
    for (int s = 16; s; s >>= 1) ss2 += __shfl_xor_sync(0xffffffffu, ss2, s);
    if (lane == 0) g_corr[row] = 0.5f * ss2;
}

// 128 tokens per block, 256 threads: thread = (token, channel-half).
__global__ void __launch_bounds__(256) norm_tokens(const float* __restrict__ z) {
    __shared__ float ssh[2][128];
    int n0 = blockIdx.x * 128;
    int b   = n0 >> 10;
    int hw0 = n0 & 1023;
    int tt = threadIdx.x & 127;
    int p  = threadIdx.x >> 7;
    const float* zp = z + ((size_t)b * CDIM + p * 128) * 1024 + hw0 + tt;

    float ss = 0.f;
    #pragma unroll 8
    for (int c = 0; c < 128; c++) { float v = zp[(size_t)c * 1024]; ss = fmaf(v, v, ss); }
    ssh[p][tt] = ss;
    __syncthreads();
    float inv = 1.0f / fmaxf(sqrtf(ssh[0][tt] + ssh[1][tt]), 1e-12f);

    int n = n0 + tt;
    ull* outp = g_zt2 + (size_t)(n >> 6) * 8192 + (n & 63);
    #pragma unroll 2
    for (int c = 0; c < 128; c += 8) {
        float v[8];
        #pragma unroll
        for (int j = 0; j < 8; j++) v[j] = zp[(size_t)(c + j) * 1024] * inv;
        #pragma unroll
        for (int q = 0; q < 4; q++) {
            int c2 = p * 64 + (c >> 1) + q;
            ull w = (ull)__float_as_uint(v[2*q]) | ((ull)__float_as_uint(v[2*q+1]) << 32);
            outp[(size_t)c2 * 64] = w;
        }
    }
}

// ---------------- main: FFMA2 GEMM + fused argmax ----------------
__global__ void __launch_bounds__(256, 2) vq_main() {
    extern __shared__ __align__(16) char smem[];
    const uint32_t sa = smem_u32(smem);
    const int tid = threadIdx.x, tc = tid & 31, tg = tid >> 5;
    const int ttile = blockIdx.x >> 1, kh = blockIdx.x & 1;

    // stage 64-token tile (64 KB), layout [c2][t] as ull
    {
        const ull* src = g_zt2 + (size_t)ttile * 8192;
        #pragma unroll
        for (int j = 0; j < 16; j++) {
            int i = tid + j * 256;
            CP16(sa + i * 16, src + (size_t)i * 2);
        }
        CP_COMMIT(); CP_WAIT0();
    }
    __syncthreads();

    const ulonglong2* tokS = (const ulonglong2*)smem;
    ull best[8];
    #pragma unroll
    for (int t = 0; t < 8; t++) best[t] = 0ull;

    for (int iter = 0; iter < 32; iter++) {
        int k0 = kh * KHALF + iter * 128 + tc * 4;
        const char* ep = (const char*)(g_en + (size_t)k0 * CDIM);

        ull acc[4][8];
        #pragma unroll
        for (int j = 0; j < 4; j++)
            #pragma unroll
            for (int t = 0; t < 8; t++) acc[j][t] = 0ull;

        ulonglong2 ec[4];
        #pragma unroll
        for (int j = 0; j < 4; j++)
            ec[j] = __ldg((const ulonglong2*)(ep + j * 1024));

        #pragma unroll 8
        for (int s = 0; s < 64; s++) {
            ulonglong2 en[4];
            if (s < 63) {
                #pragma unroll
                for (int j = 0; j < 4; j++)
                    en[j] = __ldg((const ulonglong2*)(ep + j * 1024 + (s + 1) * 16));
            }
            const ulonglong2* zp = tokS + s * 64 + tg * 4;
            ulonglong2 z0[4], z1[4];
            #pragma unroll
            for (int m = 0; m < 4; m++) { z0[m] = zp[m]; z1[m] = zp[32 + m]; }
            #pragma unroll
            for (int j = 0; j < 4; j++) {
                #pragma unroll
                for (int m = 0; m < 4; m++) {
                    ffma2(acc[j][2*m],   z0[m].x, ec[j].x);
                    ffma2(acc[j][2*m+1], z0[m].y, ec[j].x);
                    ffma2(acc[j][2*m],   z1[m].x, ec[j].y);
                    ffma2(acc[j][2*m+1], z1[m].y, ec[j].y);
                }
            }
            #pragma unroll
            for (int j = 0; j < 4; j++) ec[j] = en[j];
        }

        // epilogue: fold into running per-thread best (codes ascending)
        #pragma unroll
        for (int j = 0; j < 4; j++) {
            float corr = __ldg(&g_corr[k0 + j]);
            #pragma unroll
            for (int t = 0; t < 8; t++) {
                float sc = pair_sum(acc[j][t]) - corr;
                ull p = ((ull)fmap(sc) << 13) | (ull)(KCB - 1 - (k0 + j));
                if (p > best[t]) best[t] = p;
            }
        }
    }

    // lane reduction (32 code-lanes per warp hold the same 8 tokens)
    #pragma unroll
    for (int t = 0; t < 8; t++) {
        ull p = best[t];
        #pragma unroll
        for (int s = 16; s; s >>= 1) {
            ull o = __shfl_xor_sync(0xffffffffu, p, s);
            if (o > p) p = o;
        }
        if (tc == 0) g_top[kh][ttile * 64 + tg * 8 + t] = p;
    }
}

// ---------------- merge K-halves ----------------
__global__ void merge_halves() {
    int n = blockIdx.x * 256 + threadIdx.x;
    ull a = g_top[0][n], b = g_top[1][n];
    ull w = (b > a) ? b : a;
    g_idx[n] = (KCB - 1) - (int)(w & 0x1FFFull);
}

// ---------------- output ----------------
__global__ void __launch_bounds__(256) gather_out(float* __restrict__ out) {
    __shared__ float s[32][CDIM + 1];
    __shared__ int sidx[32];
    int n0 = blockIdx.x * 32;
    if (threadIdx.x < 32) sidx[threadIdx.x] = g_idx[n0 + threadIdx.x];
    __syncthreads();
    #pragma unroll 4
    for (int i = 0; i < 32; i++) {
        int lin = threadIdx.x + i * 256;
        int t = lin >> 8, c = lin & 255;
        s[t][c] = g_en[(size_t)sidx[t] * CDIM + c];
    }
    __syncthreads();
    int b   = n0 >> 10;
    int hw0 = n0 & 1023;
    #pragma unroll 4
    for (int i = 0; i < 32; i++) {
        int lin = threadIdx.x + i * 256;
        int c = lin >> 5, t = lin & 31;
        out[((size_t)b * CDIM + c) * 1024 + hw0 + t] = s[t][c];
    }
}

__global__ void idx_out(float* __restrict__ o) {
    int n = blockIdx.x * 256 + threadIdx.x;
    o[n] = (float)g_idx[n];
}

extern "C" void kernel_launch(void* const* d_in, const int* in_sizes, int n_in,
                              void* d_out, int out_size) {
    const float* z   = (const float*)d_in[0];
    const float* emb = (const float*)d_in[1];
    float* out = (float*)d_out;

    cudaFuncSetAttribute(vq_main, cudaFuncAttributeMaxDynamicSharedMemorySize, VQ_SMEM);

    norm_codebook<<<KCB / 8, 256>>>(emb);
    norm_tokens<<<NTOK / 128, 256>>>(z);
    vq_main<<<VQ_GRID, 256, VQ_SMEM>>>();
    merge_halves<<<NTOK / 256, 256>>>();
    gather_out<<<NTOK / 32, 256>>>(out);
    if (out_size >= OUT_ELEMS + NTOK)
        idx_out<<<NTOK / 256, 256>>>(out + OUT_ELEMS);
}

// round 7
// speedup vs baseline: 3.8511x; 3.8511x over previous
#include <cuda_runtime.h>
#include <cuda_fp16.h>
#include <cstdint>

typedef unsigned long long ull;

#define CDIM 256
#define KCB  8192
#define NTOK 16384
#define OUT_ELEMS (16*256*32*32)
#define MARGIN 1e-3f

#define VQ_SMEM (65536 + 2*32768)          // tokens + 2 code stages
#define RR_TOK  8
#define RR_ROW  260                         // 256 + 16B pad (bank spread)
#define RR_SMEM (256*RR_TOK*4 + 64*RR_ROW*4)

__device__ float   g_en[KCB * CDIM];        // normalized codebook fp32
__device__ float   g_corr[KCB];             // 0.5*|e_n|^2
__device__ __half2 g_e2[KCB * 128];         // half2 codebook, [k/64][c2][k%64]
__device__ float   g_zf[NTOK * CDIM];       // normalized tokens fp32 row-major
__device__ __half2 g_z2[NTOK * 128];        // half2 tokens, [n/128][c2][n%128]
__device__ int     g_idx[NTOK];
__device__ int     g_nflag;
__device__ int     g_list[NTOK];

// ---------------- helpers ----------------
__device__ __forceinline__ uint32_t smem_u32(const void* p) {
    uint32_t a;
    asm("{ .reg .u64 t; cvta.to.shared.u64 t, %1; cvt.u32.u64 %0, t; }" : "=r"(a) : "l"(p));
    return a;
}
#define CP16(dst, src) asm volatile("cp.async.cg.shared.global [%0], [%1], 16;" :: "r"(dst), "l"(src) : "memory")
#define CP_COMMIT()    asm volatile("cp.async.commit_group;" ::: "memory")
#define CP_WAIT1()     asm volatile("cp.async.wait_group 1;" ::: "memory")
#define CP_WAIT0()     asm volatile("cp.async.wait_group 0;" ::: "memory")

__device__ __forceinline__ unsigned fmap(float v) {
    unsigned u = __float_as_uint(v);
    return (u & 0x80000000u) ? ~u : (u | 0x80000000u);
}
__device__ __forceinline__ float funmap(unsigned u) {
    return __uint_as_float((u & 0x80000000u) ? (u ^ 0x80000000u) : ~u);
}

// ---------------- preprocessing ----------------
__global__ void norm_codebook(const float* __restrict__ emb) {
    if (blockIdx.x == 0 && threadIdx.x == 0) g_nflag = 0;
    int row  = blockIdx.x * 8 + (threadIdx.x >> 5);
    int lane = threadIdx.x & 31;
    const float4* w = (const float4*)(emb + (size_t)row * CDIM);
    float4 a = __ldg(w + lane);
    float4 b = __ldg(w + lane + 32);
    float ss = a.x*a.x + a.y*a.y + a.z*a.z + a.w*a.w
             + b.x*b.x + b.y*b.y + b.z*b.z + b.w*b.w;
    #pragma unroll
    for (int s = 16; s; s >>= 1) ss += __shfl_xor_sync(0xffffffffu, ss, s);
    float inv = 1.0f / fmaxf(sqrtf(ss), 1e-12f);
    float v[8];
    v[0]=a.x*inv; v[1]=a.y*inv; v[2]=a.z*inv; v[3]=a.w*inv;
    v[4]=b.x*inv; v[5]=b.y*inv; v[6]=b.z*inv; v[7]=b.w*inv;
    float4* o = (float4*)(g_en + (size_t)row * CDIM);
    o[lane]      = make_float4(v[0], v[1], v[2], v[3]);
    o[lane + 32] = make_float4(v[4], v[5], v[6], v[7]);
    // half2 codebook, chunk layout
    size_t base = (size_t)(row >> 6) * 8192 + (row & 63);
    g_e2[base + (size_t)(2*lane    ) * 64] = __floats2half2_rn(v[0], v[1]);
    g_e2[base + (size_t)(2*lane + 1) * 64] = __floats2half2_rn(v[2], v[3]);
    g_e2[base + (size_t)(64 + 2*lane    ) * 64] = __floats2half2_rn(v[4], v[5]);
    g_e2[base + (size_t)(64 + 2*lane + 1) * 64] = __floats2half2_rn(v[6], v[7]);
    float ss2 = 0.f;
    #pragma unroll
    for (int j = 0; j < 8; j++) ss2 = fmaf(v[j], v[j], ss2);
    #pragma unroll
    for (int s = 16; s; s >>= 1) ss2 += __shfl_xor_sync(0xffffffffu, ss2, s);
    if (lane == 0) g_corr[row] = 0.5f * ss2;
}

__global__ void __launch_bounds__(256) norm_tokens(const float* __restrict__ z) {
    __shared__ float ssh[2][128];
    int n0 = blockIdx.x * 128;
    int b   = n0 >> 10;
    int hw0 = n0 & 1023;
    int tt = threadIdx.x & 127;
    int p  = threadIdx.x >> 7;
    const float* zp = z + ((size_t)b * CDIM + p * 128) * 1024 + hw0 + tt;

    float ss = 0.f;
    #pragma unroll 8
    for (int c = 0; c < 128; c++) { float v = zp[(size_t)c * 1024]; ss = fmaf(v, v, ss); }
    ssh[p][tt] = ss;
    __syncthreads();
    float inv = 1.0f / fmaxf(sqrtf(ssh[0][tt] + ssh[1][tt]), 1e-12f);

    int n = n0 + tt;
    float* zfout = g_zf + (size_t)n * CDIM + p * 128;
    __half2* z2out = g_z2 + (size_t)blockIdx.x * 16384 + tt;
    #pragma unroll 2
    for (int c = 0; c < 128; c += 8) {
        float v[8];
        #pragma unroll
        for (int j = 0; j < 8; j++) v[j] = zp[(size_t)(c + j) * 1024] * inv;
        *(float4*)(zfout + c)     = make_float4(v[0], v[1], v[2], v[3]);
        *(float4*)(zfout + c + 4) = make_float4(v[4], v[5], v[6], v[7]);
        #pragma unroll
        for (int q = 0; q < 4; q++) {
            int c2 = p * 64 + (c >> 1) + q;
            z2out[(size_t)c2 * 128] = __floats2half2_rn(v[2*q], v[2*q+1]);
        }
    }
}

// ---------------- main: HFMA2 GEMM + fused top-2 ----------------
__global__ void __launch_bounds__(256, 1) vq_main() {
    extern __shared__ __align__(16) char smem[];
    __half2* tokS = (__half2*)smem;                       // [128 c2][128 tok]
    const uint32_t sa = smem_u32(smem);
    const int tid = threadIdx.x, tc = tid & 15, tg = tid >> 4;
    const int n0 = blockIdx.x * 128;

    // prologue: tokens (64KB) + chunk0, chunk1
    {
        const __half2* zsrc = g_z2 + (size_t)blockIdx.x * 16384;
        #pragma unroll
        for (int j = 0; j < 16; j++) { int i = tid + j*256; CP16(sa + i*16, zsrc + i*4); }
        #pragma unroll
        for (int j = 0; j < 8; j++)  { int i = tid + j*256; CP16(sa + 65536 + i*16, g_e2 + i*4); }
        CP_COMMIT();
        #pragma unroll
        for (int j = 0; j < 8; j++)  { int i = tid + j*256; CP16(sa + 65536 + 32768 + i*16, g_e2 + 8192 + i*4); }
        CP_COMMIT();
    }

    float v1[8], v2[8]; int i1[8];
    #pragma unroll
    for (int t = 0; t < 8; t++) { v1[t] = -1e30f; v2[t] = -1e30f; i1[t] = 0; }

    for (int ch = 0; ch < 128; ch++) {
        if (ch == 127) CP_WAIT0(); else CP_WAIT1();
        __syncthreads();

        const __half2* codeS = (const __half2*)(smem + 65536 + (ch & 1) * 32768);
        float facc[8][4];
        #pragma unroll
        for (int t = 0; t < 8; t++)
            #pragma unroll
            for (int j = 0; j < 4; j++) facc[t][j] = 0.f;

        #pragma unroll
        for (int seg = 0; seg < 4; seg++) {
            __half2 acc2[8][4];
            const __half2 hz = __float2half2_rn(0.f);
            #pragma unroll
            for (int t = 0; t < 8; t++)
                #pragma unroll
                for (int j = 0; j < 4; j++) acc2[t][j] = hz;

            #pragma unroll 4
            for (int cs = 0; cs < 32; cs++) {
                int c2 = seg * 32 + cs;
                __half2 zv[8], ev[4];
                *(uint4*)&zv[0] = *(const uint4*)(tokS + c2*128 + tg*8);
                *(uint4*)&zv[4] = *(const uint4*)(tokS + c2*128 + tg*8 + 4);
                *(uint4*)&ev[0] = *(const uint4*)(codeS + c2*64 + tc*4);
                #pragma unroll
                for (int t = 0; t < 8; t++)
                    #pragma unroll
                    for (int j = 0; j < 4; j++)
                        acc2[t][j] = __hfma2(zv[t], ev[j], acc2[t][j]);
            }
            #pragma unroll
            for (int t = 0; t < 8; t++)
                #pragma unroll
                for (int j = 0; j < 4; j++)
                    facc[t][j] += __low2float(acc2[t][j]) + __high2float(acc2[t][j]);
        }
        __syncthreads();

        if (ch + 2 < 128) {
            const __half2* esrc = g_e2 + (size_t)(ch + 2) * 8192;
            uint32_t db = sa + 65536 + (ch & 1) * 32768;
            #pragma unroll
            for (int j = 0; j < 8; j++) { int i = tid + j*256; CP16(db + i*16, esrc + i*4); }
        }
        CP_COMMIT();

        int kbase = ch * 64 + tc * 4;
        #pragma unroll
        for (int t = 0; t < 8; t++)
            #pragma unroll
            for (int j = 0; j < 4; j++) {
                float s = facc[t][j];
                if (s > v1[t]) { v2[t] = v1[t]; v1[t] = s; i1[t] = kbase + j; }
                else if (s > v2[t]) v2[t] = s;
            }
    }

    // reduce over the 16 code-lanes (half-warp)
    #pragma unroll
    for (int t = 0; t < 8; t++) {
        ull p = ((ull)fmap(v1[t]) << 13) | (ull)(8191 - i1[t]);
        float s2 = v2[t];
        #pragma unroll
        for (int x = 1; x <= 8; x <<= 1) {
            ull po = __shfl_xor_sync(0xffffffffu, p, x);
            float s2o = __shfl_xor_sync(0xffffffffu, s2, x);
            float va = funmap((unsigned)(p >> 13));
            float vb = funmap((unsigned)(po >> 13));
            s2 = fmaxf(fmaxf(s2, s2o), fminf(va, vb));
            if (po > p) p = po;
        }
        if (tc == 0) {
            int n = n0 + tg * 8 + t;
            g_idx[n] = 8191 - (int)(p & 0x1FFF);
            float mg = funmap((unsigned)(p >> 13)) - s2;
            if (mg < MARGIN) {
                int pos = atomicAdd(&g_nflag, 1);
                g_list[pos] = n;
            }
        }
    }
}

// ---------------- batched exact fp32 re-rank (8 flagged tokens / block) ----------------
__global__ void __launch_bounds__(256) rerank8() {
    int base = blockIdx.x * RR_TOK;
    int cnt = *(volatile int*)&g_nflag;
    if (base >= cnt) return;

    extern __shared__ __align__(16) float rsm[];
    float* tz = rsm;                          // [256 c][8 tok]
    float* ec = rsm + 256 * RR_TOK;           // [64 code][RR_ROW]
    const uint32_t eca = smem_u32(ec);

    int tid = threadIdx.x;
    int tp  = tid >> 6;            // token pair 0..3
    int cl  = tid & 63;            // code lane

    // stage tokens
    for (int i = tid; i < 256 * RR_TOK; i += 256) {
        int tok = i >> 8, c = i & 255;
        float v = 0.f;
        if (base + tok < cnt) v = g_zf[(size_t)g_list[base + tok] * CDIM + c];
        tz[c * RR_TOK + tok] = v;
    }
    __syncthreads();

    ull best0 = 0ull, best1 = 0ull;
    for (int chunk = 0; chunk < 128; chunk++) {
        int k0 = chunk * 64;
        // load 64 codebook rows (coalesced), padded rows
        #pragma unroll
        for (int r = 0; r < 16; r++) {
            int i = tid + r * 256;
            int code = i >> 6, seg = i & 63;
            CP16(eca + (code * RR_ROW + seg * 4) * 4, g_en + (size_t)(k0 + code) * CDIM + seg * 4);
        }
        CP_COMMIT(); CP_WAIT0();
        __syncthreads();

        float s0 = 0.f, s1 = 0.f;
        const float* erow = ec + cl * RR_ROW;
        #pragma unroll 8
        for (int c = 0; c < 256; c++) {
            float ee = erow[c];
            float2 zz = *(const float2*)(tz + c * RR_TOK + tp * 2);
            s0 = fmaf(zz.x, ee, s0);
            s1 = fmaf(zz.y, ee, s1);
        }
        int k = k0 + cl;
        float corr = __ldg(&g_corr[k]);
        s0 -= corr; s1 -= corr;
        ull p0 = ((ull)fmap(s0) << 13) | (ull)(8191 - k);
        ull p1 = ((ull)fmap(s1) << 13) | (ull)(8191 - k);
        if (p0 > best0) best0 = p0;
        if (p1 > best1) best1 = p1;
        __syncthreads();
    }

    __shared__ ull red[8][2];
    #pragma unroll
    for (int x = 16; x; x >>= 1) {
        ull o0 = __shfl_xor_sync(0xffffffffu, best0, x);
        ull o1 = __shfl_xor_sync(0xffffffffu, best1, x);
        if (o0 > best0) best0 = o0;
        if (o1 > best1) best1 = o1;
    }
    int warp = tid >> 5;
    if ((tid & 31) == 0) { red[warp][0] = best0; red[warp][1] = best1; }
    __syncthreads();
    if (tid < RR_TOK) {
        int tpp = tid >> 1, i = tid & 1;
        ull a = red[tpp*2][i], b = red[tpp*2 + 1][i];
        ull p = (b > a) ? b : a;
        if (base + tid < cnt) {
            int n = g_list[base + tid];
            g_idx[n] = 8191 - (int)(p & 0x1FFF);
        }
    }
}

// ---------------- output ----------------
__global__ void __launch_bounds__(256) gather_out(float* __restrict__ out) {
    __shared__ float s[32][CDIM + 1];
    __shared__ int sidx[32];
    int n0 = blockIdx.x * 32;
    if (threadIdx.x < 32) sidx[threadIdx.x] = g_idx[n0 + threadIdx.x];
    __syncthreads();
    #pragma unroll 4
    for (int i = 0; i < 32; i++) {
        int lin = threadIdx.x + i * 256;
        int t = lin >> 8, c = lin & 255;
        s[t][c] = g_en[(size_t)sidx[t] * CDIM + c];
    }
    __syncthreads();
    int b   = n0 >> 10;
    int hw0 = n0 & 1023;
    #pragma unroll 4
    for (int i = 0; i < 32; i++) {
        int lin = threadIdx.x + i * 256;
        int c = lin >> 5, t = lin & 31;
        out[((size_t)b * CDIM + c) * 1024 + hw0 + t] = s[t][c];
    }
}

__global__ void idx_out(float* __restrict__ o) {
    int n = blockIdx.x * 256 + threadIdx.x;
    o[n] = (float)g_idx[n];
}

extern "C" void kernel_launch(void* const* d_in, const int* in_sizes, int n_in,
                              void* d_out, int out_size) {
    const float* z   = (const float*)d_in[0];
    const float* emb = (const float*)d_in[1];
    float* out = (float*)d_out;

    cudaFuncSetAttribute(vq_main,  cudaFuncAttributeMaxDynamicSharedMemorySize, VQ_SMEM);
    cudaFuncSetAttribute(rerank8,  cudaFuncAttributeMaxDynamicSharedMemorySize, RR_SMEM);

    norm_codebook<<<KCB / 8, 256>>>(emb);
    norm_tokens<<<NTOK / 128, 256>>>(z);
    vq_main<<<NTOK / 128, 256, VQ_SMEM>>>();
    rerank8<<<NTOK / RR_TOK, 256, RR_SMEM>>>();
    gather_out<<<NTOK / 32, 256>>>(out);
    if (out_size >= OUT_ELEMS + NTOK)
        idx_out<<<NTOK / 256, 256>>>(out + OUT_ELEMS);
}

// round 8
// speedup vs baseline: 4.8186x; 1.2512x over previous
#include <cuda_runtime.h>
#include <cuda_fp16.h>
#include <cstdint>

typedef unsigned long long ull;

#define CDIM 256
#define KCB  8192
#define NTOK 16384
#define OUT_ELEMS (16*256*32*32)
#define MARGIN 1e-3f

#define VQ_SMEM (65536 + 2*32768)          // tokens + 2 code stages
#define RR_SMEM (65536 + 16384 + 256)      // codes [c4][64] + 16 tokens + red

__device__ float   g_en[KCB * CDIM];        // normalized codebook fp32
__device__ float   g_corr[KCB];             // 0.5*|e_n|^2
__device__ __half2 g_e2[KCB * 128];         // half2 codebook, [k/64][c2][k%64]
__device__ float   g_zf[NTOK * CDIM];       // normalized tokens fp32 row-major
__device__ __half2 g_z2[NTOK * 128];        // half2 tokens, [n/128][c2][n%128]
__device__ int     g_idx[NTOK];
__device__ int     g_nflag;
__device__ int     g_list[NTOK];
__device__ ull     g_bestm[NTOK];

// ---------------- helpers ----------------
__device__ __forceinline__ uint32_t smem_u32(const void* p) {
    uint32_t a;
    asm("{ .reg .u64 t; cvta.to.shared.u64 t, %1; cvt.u32.u64 %0, t; }" : "=r"(a) : "l"(p));
    return a;
}
#define CP16(dst, src) asm volatile("cp.async.cg.shared.global [%0], [%1], 16;" :: "r"(dst), "l"(src) : "memory")
#define CP_COMMIT()    asm volatile("cp.async.commit_group;" ::: "memory")
#define CP_WAIT1()     asm volatile("cp.async.wait_group 1;" ::: "memory")
#define CP_WAIT0()     asm volatile("cp.async.wait_group 0;" ::: "memory")

__device__ __forceinline__ unsigned fmap(float v) {
    unsigned u = __float_as_uint(v);
    return (u & 0x80000000u) ? ~u : (u | 0x80000000u);
}
__device__ __forceinline__ float funmap(unsigned u) {
    return __uint_as_float((u & 0x80000000u) ? (u ^ 0x80000000u) : ~u);
}

// ---------------- preprocessing ----------------
__global__ void norm_codebook(const float* __restrict__ emb) {
    if (blockIdx.x == 0 && threadIdx.x == 0) g_nflag = 0;
    int row  = blockIdx.x * 8 + (threadIdx.x >> 5);
    int lane = threadIdx.x & 31;
    const float4* w = (const float4*)(emb + (size_t)row * CDIM);
    float4 a = __ldg(w + lane);
    float4 b = __ldg(w + lane + 32);
    float ss = a.x*a.x + a.y*a.y + a.z*a.z + a.w*a.w
             + b.x*b.x + b.y*b.y + b.z*b.z + b.w*b.w;
    #pragma unroll
    for (int s = 16; s; s >>= 1) ss += __shfl_xor_sync(0xffffffffu, ss, s);
    float inv = 1.0f / fmaxf(sqrtf(ss), 1e-12f);
    float v[8];
    v[0]=a.x*inv; v[1]=a.y*inv; v[2]=a.z*inv; v[3]=a.w*inv;
    v[4]=b.x*inv; v[5]=b.y*inv; v[6]=b.z*inv; v[7]=b.w*inv;
    float4* o = (float4*)(g_en + (size_t)row * CDIM);
    o[lane]      = make_float4(v[0], v[1], v[2], v[3]);
    o[lane + 32] = make_float4(v[4], v[5], v[6], v[7]);
    size_t base = (size_t)(row >> 6) * 8192 + (row & 63);
    g_e2[base + (size_t)(2*lane    ) * 64] = __floats2half2_rn(v[0], v[1]);
    g_e2[base + (size_t)(2*lane + 1) * 64] = __floats2half2_rn(v[2], v[3]);
    g_e2[base + (size_t)(64 + 2*lane    ) * 64] = __floats2half2_rn(v[4], v[5]);
    g_e2[base + (size_t)(64 + 2*lane + 1) * 64] = __floats2half2_rn(v[6], v[7]);
    float ss2 = 0.f;
    #pragma unroll
    for (int j = 0; j < 8; j++) ss2 = fmaf(v[j], v[j], ss2);
    #pragma unroll
    for (int s = 16; s; s >>= 1) ss2 += __shfl_xor_sync(0xffffffffu, ss2, s);
    if (lane == 0) g_corr[row] = 0.5f * ss2;
}

__global__ void __launch_bounds__(256) norm_tokens(const float* __restrict__ z) {
    __shared__ float ssh[2][128];
    int n0 = blockIdx.x * 128;
    int b   = n0 >> 10;
    int hw0 = n0 & 1023;
    int tt = threadIdx.x & 127;
    int p  = threadIdx.x >> 7;
    const float* zp = z + ((size_t)b * CDIM + p * 128) * 1024 + hw0 + tt;

    float ss = 0.f;
    #pragma unroll 8
    for (int c = 0; c < 128; c++) { float v = zp[(size_t)c * 1024]; ss = fmaf(v, v, ss); }
    ssh[p][tt] = ss;
    __syncthreads();
    float inv = 1.0f / fmaxf(sqrtf(ssh[0][tt] + ssh[1][tt]), 1e-12f);

    int n = n0 + tt;
    float* zfout = g_zf + (size_t)n * CDIM + p * 128;
    __half2* z2out = g_z2 + (size_t)blockIdx.x * 16384 + tt;
    #pragma unroll 2
    for (int c = 0; c < 128; c += 8) {
        float v[8];
        #pragma unroll
        for (int j = 0; j < 8; j++) v[j] = zp[(size_t)(c + j) * 1024] * inv;
        *(float4*)(zfout + c)     = make_float4(v[0], v[1], v[2], v[3]);
        *(float4*)(zfout + c + 4) = make_float4(v[4], v[5], v[6], v[7]);
        #pragma unroll
        for (int q = 0; q < 4; q++) {
            int c2 = p * 64 + (c >> 1) + q;
            z2out[(size_t)c2 * 128] = __floats2half2_rn(v[2*q], v[2*q+1]);
        }
    }
}

// ---------------- main: HFMA2 GEMM + fused top-2 ----------------
__global__ void __launch_bounds__(256, 1) vq_main() {
    extern __shared__ __align__(16) char smem[];
    __half2* tokS = (__half2*)smem;                       // [128 c2][128 tok]
    const uint32_t sa = smem_u32(smem);
    const int tid = threadIdx.x, tc = tid & 15, tg = tid >> 4;
    const int n0 = blockIdx.x * 128;

    {
        const __half2* zsrc = g_z2 + (size_t)blockIdx.x * 16384;
        #pragma unroll
        for (int j = 0; j < 16; j++) { int i = tid + j*256; CP16(sa + i*16, zsrc + i*4); }
        #pragma unroll
        for (int j = 0; j < 8; j++)  { int i = tid + j*256; CP16(sa + 65536 + i*16, g_e2 + i*4); }
        CP_COMMIT();
        #pragma unroll
        for (int j = 0; j < 8; j++)  { int i = tid + j*256; CP16(sa + 65536 + 32768 + i*16, g_e2 + 8192 + i*4); }
        CP_COMMIT();
    }

    float v1[8], v2[8]; int i1[8];
    #pragma unroll
    for (int t = 0; t < 8; t++) { v1[t] = -1e30f; v2[t] = -1e30f; i1[t] = 0; }

    for (int ch = 0; ch < 128; ch++) {
        if (ch == 127) CP_WAIT0(); else CP_WAIT1();
        __syncthreads();

        const __half2* codeS = (const __half2*)(smem + 65536 + (ch & 1) * 32768);
        float facc[8][4];
        #pragma unroll
        for (int t = 0; t < 8; t++)
            #pragma unroll
            for (int j = 0; j < 4; j++) facc[t][j] = 0.f;

        #pragma unroll
        for (int seg = 0; seg < 4; seg++) {
            __half2 acc2[8][4];
            const __half2 hz = __float2half2_rn(0.f);
            #pragma unroll
            for (int t = 0; t < 8; t++)
                #pragma unroll
                for (int j = 0; j < 4; j++) acc2[t][j] = hz;

            #pragma unroll 4
            for (int cs = 0; cs < 32; cs++) {
                int c2 = seg * 32 + cs;
                __half2 zv[8], ev[4];
                *(uint4*)&zv[0] = *(const uint4*)(tokS + c2*128 + tg*8);
                *(uint4*)&zv[4] = *(const uint4*)(tokS + c2*128 + tg*8 + 4);
                *(uint4*)&ev[0] = *(const uint4*)(codeS + c2*64 + tc*4);
                #pragma unroll
                for (int t = 0; t < 8; t++)
                    #pragma unroll
                    for (int j = 0; j < 4; j++)
                        acc2[t][j] = __hfma2(zv[t], ev[j], acc2[t][j]);
            }
            #pragma unroll
            for (int t = 0; t < 8; t++)
                #pragma unroll
                for (int j = 0; j < 4; j++)
                    facc[t][j] += __low2float(acc2[t][j]) + __high2float(acc2[t][j]);
        }
        __syncthreads();

        if (ch + 2 < 128) {
            const __half2* esrc = g_e2 + (size_t)(ch + 2) * 8192;
            uint32_t db = sa + 65536 + (ch & 1) * 32768;
            #pragma unroll
            for (int j = 0; j < 8; j++) { int i = tid + j*256; CP16(db + i*16, esrc + i*4); }
        }
        CP_COMMIT();

        int kbase = ch * 64 + tc * 4;
        #pragma unroll
        for (int t = 0; t < 8; t++)
            #pragma unroll
            for (int j = 0; j < 4; j++) {
                float s = facc[t][j];
                if (s > v1[t]) { v2[t] = v1[t]; v1[t] = s; i1[t] = kbase + j; }
                else if (s > v2[t]) v2[t] = s;
            }
    }

    #pragma unroll
    for (int t = 0; t < 8; t++) {
        ull p = ((ull)fmap(v1[t]) << 13) | (ull)(8191 - i1[t]);
        float s2 = v2[t];
        #pragma unroll
        for (int x = 1; x <= 8; x <<= 1) {
            ull po = __shfl_xor_sync(0xffffffffu, p, x);
            float s2o = __shfl_xor_sync(0xffffffffu, s2, x);
            float va = funmap((unsigned)(p >> 13));
            float vb = funmap((unsigned)(po >> 13));
            s2 = fmaxf(fmaxf(s2, s2o), fminf(va, vb));
            if (po > p) p = po;
        }
        if (tc == 0) {
            int n = n0 + tg * 8 + t;
            g_idx[n] = 8191 - (int)(p & 0x1FFF);
            float mg = funmap((unsigned)(p >> 13)) - s2;
            if (mg < MARGIN) {
                g_bestm[n] = 0ull;
                int pos = atomicAdd(&g_nflag, 1);
                g_list[pos] = n;
            }
        }
    }
}

// ---------------- rerank: 128 blocks x 64 codes, stream flagged tokens ----------------
__global__ void __launch_bounds__(256, 1) rerank_part() {
    int cnt = *(volatile int*)&g_nflag;
    if (cnt == 0) return;

    extern __shared__ __align__(16) char rsm[];
    float4* ecv = (float4*)rsm;                 // [64 c4][64 code]
    float4* tzv = (float4*)(rsm + 65536);       // [16 tok][64 c4]
    ull*    red = (ull*)(rsm + 65536 + 16384);  // [4 g][4 t][2 w]

    const int tid = threadIdx.x;
    const int cl  = tid & 63;                    // code lane 0..63
    const int g   = tid >> 6;                    // token group 0..3
    const int k0  = blockIdx.x * 64;
    const int k   = k0 + cl;
    const float corr = __ldg(&g_corr[k]);

    // stage codes: thread (cl, seg=g) loads 16 float4 of row k, seg chunk
    {
        const float4* src = (const float4*)(g_en + (size_t)k * CDIM) + g * 16;
        #pragma unroll
        for (int j = 0; j < 16; j++) {
            float4 vv = __ldg(src + j);
            ecv[(g * 16 + j) * 64 + cl] = vv;
        }
    }
    __syncthreads();

    const int witer = (cnt + 15) >> 4;
    for (int it = 0; it < witer; it++) {
        // stage 16 tokens (1024 float4, 4 per thread)
        #pragma unroll
        for (int j = 0; j < 4; j++) {
            int i = tid + j * 256;
            int tok = i >> 6, c4 = i & 63;
            int li = it * 16 + tok;
            int n = g_list[(li < cnt) ? li : 0];
            tzv[tok * 64 + c4] = __ldg((const float4*)(g_zf + (size_t)n * CDIM) + c4);
        }
        __syncthreads();

        float s[4];
        #pragma unroll
        for (int t = 0; t < 4; t++) s[t] = 0.f;
        const float4* tz0 = tzv + (g * 4) * 64;
        #pragma unroll 8
        for (int c4 = 0; c4 < 64; c4++) {
            float4 ev = ecv[c4 * 64 + cl];
            #pragma unroll
            for (int t = 0; t < 4; t++) {
                float4 zz = tz0[t * 64 + c4];
                s[t] = fmaf(zz.x, ev.x, s[t]);
                s[t] = fmaf(zz.y, ev.y, s[t]);
                s[t] = fmaf(zz.z, ev.z, s[t]);
                s[t] = fmaf(zz.w, ev.w, s[t]);
            }
        }
        __syncthreads();

        // reduce over 64 code lanes (2 warps per group), then atomic merge
        #pragma unroll
        for (int t = 0; t < 4; t++) {
            ull p = ((ull)fmap(s[t] - corr) << 13) | (ull)(8191 - k);
            #pragma unroll
            for (int x = 16; x; x >>= 1) {
                ull o = __shfl_xor_sync(0xffffffffu, p, x);
                if (o > p) p = o;
            }
            if ((tid & 31) == 0) red[(g * 4 + t) * 2 + ((tid >> 5) & 1)] = p;
        }
        __syncthreads();
        if ((tid & 63) < 4) {
            int t = tid & 63;
            int li = it * 16 + g * 4 + t;
            if (li < cnt) {
                ull a = red[(g * 4 + t) * 2], b = red[(g * 4 + t) * 2 + 1];
                ull p = (b > a) ? b : a;
                atomicMax(&g_bestm[g_list[li]], p);
            }
        }
        __syncthreads();
    }
}

__global__ void rerank_fix() {
    int i = blockIdx.x * 256 + threadIdx.x;
    if (i < *(volatile int*)&g_nflag) {
        int n = g_list[i];
        g_idx[n] = 8191 - (int)(g_bestm[n] & 0x1FFF);
    }
}

// ---------------- output ----------------
__global__ void __launch_bounds__(256) gather_out(float* __restrict__ out) {
    __shared__ float s[32][CDIM + 1];
    __shared__ int sidx[32];
    int n0 = blockIdx.x * 32;
    if (threadIdx.x < 32) sidx[threadIdx.x] = g_idx[n0 + threadIdx.x];
    __syncthreads();
    #pragma unroll 4
    for (int i = 0; i < 32; i++) {
        int lin = threadIdx.x + i * 256;
        int t = lin >> 8, c = lin & 255;
        s[t][c] = g_en[(size_t)sidx[t] * CDIM + c];
    }
    __syncthreads();
    int b   = n0 >> 10;
    int hw0 = n0 & 1023;
    #pragma unroll 4
    for (int i = 0; i < 32; i++) {
        int lin = threadIdx.x + i * 256;
        int c = lin >> 5, t = lin & 31;
        out[((size_t)b * CDIM + c) * 1024 + hw0 + t] = s[t][c];
    }
}

__global__ void idx_out(float* __restrict__ o) {
    int n = blockIdx.x * 256 + threadIdx.x;
    o[n] = (float)g_idx[n];
}

extern "C" void kernel_launch(void* const* d_in, const int* in_sizes, int n_in,
                              void* d_out, int out_size) {
    const float* z   = (const float*)d_in[0];
    const float* emb = (const float*)d_in[1];
    float* out = (float*)d_out;

    cudaFuncSetAttribute(vq_main,     cudaFuncAttributeMaxDynamicSharedMemorySize, VQ_SMEM);
    cudaFuncSetAttribute(rerank_part, cudaFuncAttributeMaxDynamicSharedMemorySize, RR_SMEM);

    norm_codebook<<<KCB / 8, 256>>>(emb);
    norm_tokens<<<NTOK / 128, 256>>>(z);
    vq_main<<<NTOK / 128, 256, VQ_SMEM>>>();
    rerank_part<<<128, 256, RR_SMEM>>>();
    rerank_fix<<<NTOK / 256, 256>>>();
    gather_out<<<NTOK / 32, 256>>>(out);
    if (out_size >= OUT_ELEMS + NTOK)
        idx_out<<<NTOK / 256, 256>>>(out + OUT_ELEMS);
}

// round 9
// speedup vs baseline: 4.9047x; 1.0179x over previous
#include <cuda_runtime.h>
#include <cuda_fp16.h>
#include <cstdint>

typedef unsigned long long ull;

#define CDIM 256
#define KCB  8192
#define NTOK 16384
#define OUT_ELEMS (16*256*32*32)
#define MARGIN 6e-4f

#define VQ_SMEM (65536 + 2*32768)            // tokens + 2 code stages
#define RR_SMEM (65536 + 32768 + 512)        // codes [c4][64] + 32 tokens + red

__device__ float   g_en[KCB * CDIM];         // normalized codebook fp32
__device__ float   g_corr[KCB];              // 0.5*|e_n|^2
__device__ __half2 g_e2[KCB * 128];          // half2 codebook, [k/64][c2][k%64]
__device__ float   g_zf[NTOK * CDIM];        // normalized tokens fp32 row-major
__device__ __half2 g_z2[NTOK * 128];         // half2 tokens, [n/128][c2][n%128]
__device__ int     g_idx[NTOK];
__device__ int     g_nflag;
__device__ int     g_list[NTOK];
__device__ ull     g_bestm[NTOK];

// ---------------- helpers ----------------
__device__ __forceinline__ uint32_t smem_u32(const void* p) {
    uint32_t a;
    asm("{ .reg .u64 t; cvta.to.shared.u64 t, %1; cvt.u32.u64 %0, t; }" : "=r"(a) : "l"(p));
    return a;
}
#define CP16(dst, src) asm volatile("cp.async.cg.shared.global [%0], [%1], 16;" :: "r"(dst), "l"(src) : "memory")
#define CP_COMMIT()    asm volatile("cp.async.commit_group;" ::: "memory")
#define CP_WAIT1()     asm volatile("cp.async.wait_group 1;" ::: "memory")
#define CP_WAIT0()     asm volatile("cp.async.wait_group 0;" ::: "memory")

__device__ __forceinline__ unsigned fmap(float v) {
    unsigned u = __float_as_uint(v);
    return (u & 0x80000000u) ? ~u : (u | 0x80000000u);
}
__device__ __forceinline__ float funmap(unsigned u) {
    return __uint_as_float((u & 0x80000000u) ? (u ^ 0x80000000u) : ~u);
}

// ---------------- preprocessing ----------------
__global__ void norm_codebook(const float* __restrict__ emb) {
    if (blockIdx.x == 0 && threadIdx.x == 0) g_nflag = 0;
    int row  = blockIdx.x * 8 + (threadIdx.x >> 5);
    int lane = threadIdx.x & 31;
    const float4* w = (const float4*)(emb + (size_t)row * CDIM);
    float4 a = __ldg(w + lane);
    float4 b = __ldg(w + lane + 32);
    float ss = a.x*a.x + a.y*a.y + a.z*a.z + a.w*a.w
             + b.x*b.x + b.y*b.y + b.z*b.z + b.w*b.w;
    #pragma unroll
    for (int s = 16; s; s >>= 1) ss += __shfl_xor_sync(0xffffffffu, ss, s);
    float inv = 1.0f / fmaxf(sqrtf(ss), 1e-12f);
    float v[8];
    v[0]=a.x*inv; v[1]=a.y*inv; v[2]=a.z*inv; v[3]=a.w*inv;
    v[4]=b.x*inv; v[5]=b.y*inv; v[6]=b.z*inv; v[7]=b.w*inv;
    float4* o = (float4*)(g_en + (size_t)row * CDIM);
    o[lane]      = make_float4(v[0], v[1], v[2], v[3]);
    o[lane + 32] = make_float4(v[4], v[5], v[6], v[7]);
    size_t base = (size_t)(row >> 6) * 8192 + (row & 63);
    g_e2[base + (size_t)(2*lane    ) * 64] = __floats2half2_rn(v[0], v[1]);
    g_e2[base + (size_t)(2*lane + 1) * 64] = __floats2half2_rn(v[2], v[3]);
    g_e2[base + (size_t)(64 + 2*lane    ) * 64] = __floats2half2_rn(v[4], v[5]);
    g_e2[base + (size_t)(64 + 2*lane + 1) * 64] = __floats2half2_rn(v[6], v[7]);
    float ss2 = 0.f;
    #pragma unroll
    for (int j = 0; j < 8; j++) ss2 = fmaf(v[j], v[j], ss2);
    #pragma unroll
    for (int s = 16; s; s >>= 1) ss2 += __shfl_xor_sync(0xffffffffu, ss2, s);
    if (lane == 0) g_corr[row] = 0.5f * ss2;
}

__global__ void __launch_bounds__(256) norm_tokens(const float* __restrict__ z) {
    __shared__ float ssh[2][128];
    int n0 = blockIdx.x * 128;
    int b   = n0 >> 10;
    int hw0 = n0 & 1023;
    int tt = threadIdx.x & 127;
    int p  = threadIdx.x >> 7;
    const float* zp = z + ((size_t)b * CDIM + p * 128) * 1024 + hw0 + tt;

    float ss = 0.f;
    #pragma unroll 8
    for (int c = 0; c < 128; c++) { float v = zp[(size_t)c * 1024]; ss = fmaf(v, v, ss); }
    ssh[p][tt] = ss;
    __syncthreads();
    float inv = 1.0f / fmaxf(sqrtf(ssh[0][tt] + ssh[1][tt]), 1e-12f);

    int n = n0 + tt;
    float* zfout = g_zf + (size_t)n * CDIM + p * 128;
    __half2* z2out = g_z2 + (size_t)blockIdx.x * 16384 + tt;
    #pragma unroll 2
    for (int c = 0; c < 128; c += 8) {
        float v[8];
        #pragma unroll
        for (int j = 0; j < 8; j++) v[j] = zp[(size_t)(c + j) * 1024] * inv;
        *(float4*)(zfout + c)     = make_float4(v[0], v[1], v[2], v[3]);
        *(float4*)(zfout + c + 4) = make_float4(v[4], v[5], v[6], v[7]);
        #pragma unroll
        for (int q = 0; q < 4; q++) {
            int c2 = p * 64 + (c >> 1) + q;
            z2out[(size_t)c2 * 128] = __floats2half2_rn(v[2*q], v[2*q+1]);
        }
    }
}

// ---------------- main: HFMA2 GEMM (split accumulators) + fused top-2 ----------------
__global__ void __launch_bounds__(256, 1) vq_main() {
    extern __shared__ __align__(16) char smem[];
    __half2* tokS = (__half2*)smem;                       // [128 c2][128 tok]
    const uint32_t sa = smem_u32(smem);
    const int tid = threadIdx.x, tc = tid & 15, tg = tid >> 4;
    const int n0 = blockIdx.x * 128;

    {
        const __half2* zsrc = g_z2 + (size_t)blockIdx.x * 16384;
        #pragma unroll
        for (int j = 0; j < 16; j++) { int i = tid + j*256; CP16(sa + i*16, zsrc + i*4); }
        #pragma unroll
        for (int j = 0; j < 8; j++)  { int i = tid + j*256; CP16(sa + 65536 + i*16, g_e2 + i*4); }
        CP_COMMIT();
        #pragma unroll
        for (int j = 0; j < 8; j++)  { int i = tid + j*256; CP16(sa + 65536 + 32768 + i*16, g_e2 + 8192 + i*4); }
        CP_COMMIT();
    }

    float v1[8], v2[8]; int i1[8];
    #pragma unroll
    for (int t = 0; t < 8; t++) { v1[t] = -1e30f; v2[t] = -1e30f; i1[t] = 0; }

    for (int ch = 0; ch < 128; ch++) {
        if (ch == 127) CP_WAIT0(); else CP_WAIT1();
        __syncthreads();

        const __half2* codeS = (const __half2*)(smem + 65536 + (ch & 1) * 32768);
        float facc[8][4];
        #pragma unroll
        for (int t = 0; t < 8; t++)
            #pragma unroll
            for (int j = 0; j < 4; j++) facc[t][j] = 0.f;

        #pragma unroll
        for (int seg = 0; seg < 4; seg++) {
            __half2 acc2[2][8][4];                       // parity-split chains
            const __half2 hz = __float2half2_rn(0.f);
            #pragma unroll
            for (int pp = 0; pp < 2; pp++)
                #pragma unroll
                for (int t = 0; t < 8; t++)
                    #pragma unroll
                    for (int j = 0; j < 4; j++) acc2[pp][t][j] = hz;

            #pragma unroll 4
            for (int cs = 0; cs < 32; cs++) {
                int c2 = seg * 32 + cs;
                int pp = cs & 1;
                __half2 zv[8], ev[4];
                *(uint4*)&zv[0] = *(const uint4*)(tokS + c2*128 + tg*8);
                *(uint4*)&zv[4] = *(const uint4*)(tokS + c2*128 + tg*8 + 4);
                *(uint4*)&ev[0] = *(const uint4*)(codeS + c2*64 + tc*4);
                #pragma unroll
                for (int t = 0; t < 8; t++)
                    #pragma unroll
                    for (int j = 0; j < 4; j++)
                        acc2[pp][t][j] = __hfma2(zv[t], ev[j], acc2[pp][t][j]);
            }
            #pragma unroll
            for (int t = 0; t < 8; t++)
                #pragma unroll
                for (int j = 0; j < 4; j++)
                    facc[t][j] += (__low2float(acc2[0][t][j]) + __high2float(acc2[0][t][j]))
                                + (__low2float(acc2[1][t][j]) + __high2float(acc2[1][t][j]));
        }
        __syncthreads();

        if (ch + 2 < 128) {
            const __half2* esrc = g_e2 + (size_t)(ch + 2) * 8192;
            uint32_t db = sa + 65536 + (ch & 1) * 32768;
            #pragma unroll
            for (int j = 0; j < 8; j++) { int i = tid + j*256; CP16(db + i*16, esrc + i*4); }
        }
        CP_COMMIT();

        int kbase = ch * 64 + tc * 4;
        #pragma unroll
        for (int t = 0; t < 8; t++)
            #pragma unroll
            for (int j = 0; j < 4; j++) {
                float s = facc[t][j];
                if (s > v1[t]) { v2[t] = v1[t]; v1[t] = s; i1[t] = kbase + j; }
                else if (s > v2[t]) v2[t] = s;
            }
    }

    #pragma unroll
    for (int t = 0; t < 8; t++) {
        ull p = ((ull)fmap(v1[t]) << 13) | (ull)(8191 - i1[t]);
        float s2 = v2[t];
        #pragma unroll
        for (int x = 1; x <= 8; x <<= 1) {
            ull po = __shfl_xor_sync(0xffffffffu, p, x);
            float s2o = __shfl_xor_sync(0xffffffffu, s2, x);
            float va = funmap((unsigned)(p >> 13));
            float vb = funmap((unsigned)(po >> 13));
            s2 = fmaxf(fmaxf(s2, s2o), fminf(va, vb));
            if (po > p) p = po;
        }
        if (tc == 0) {
            int n = n0 + tg * 8 + t;
            g_idx[n] = 8191 - (int)(p & 0x1FFF);
            float mg = funmap((unsigned)(p >> 13)) - s2;
            if (mg < MARGIN) {
                g_bestm[n] = 0ull;
                int pos = atomicAdd(&g_nflag, 1);
                g_list[pos] = n;
            }
        }
    }
}

// ---------------- rerank: 128 blocks x 64 codes, 32 tokens/iter, 8 tok/thread ----------------
__global__ void __launch_bounds__(256, 1) rerank_part() {
    int cnt = *(volatile int*)&g_nflag;
    if (cnt == 0) return;

    extern __shared__ __align__(16) char rsm[];
    float4* ecv = (float4*)rsm;                 // [64 c4][64 code]
    float4* tzv = (float4*)(rsm + 65536);       // [32 tok][64 c4]
    ull*    red = (ull*)(rsm + 65536 + 32768);  // [32 tok][2 w]

    const int tid = threadIdx.x;
    const int cl  = tid & 63;                    // code lane 0..63
    const int g   = tid >> 6;                    // token group 0..3 (8 tokens each)
    const int k0  = blockIdx.x * 64;
    const int k   = k0 + cl;
    const float corr = __ldg(&g_corr[k]);

    // stage codes: [c4][code] layout
    {
        const float4* src = (const float4*)(g_en + (size_t)k * CDIM) + g * 16;
        #pragma unroll
        for (int j = 0; j < 16; j++) {
            float4 vv = __ldg(src + j);
            ecv[(g * 16 + j) * 64 + cl] = vv;
        }
    }
    __syncthreads();

    const int witer = (cnt + 31) >> 5;
    for (int it = 0; it < witer; it++) {
        // stage 32 tokens (2048 float4, 8 per thread)
        #pragma unroll
        for (int j = 0; j < 8; j++) {
            int i = tid + j * 256;
            int tok = i >> 6, c4 = i & 63;
            int li = it * 32 + tok;
            int n = g_list[(li < cnt) ? li : 0];
            tzv[tok * 64 + c4] = __ldg((const float4*)(g_zf + (size_t)n * CDIM) + c4);
        }
        __syncthreads();

        float s[8];
        #pragma unroll
        for (int t = 0; t < 8; t++) s[t] = 0.f;
        const float4* tz0 = tzv + (g * 8) * 64;
        #pragma unroll 4
        for (int c4 = 0; c4 < 64; c4++) {
            float4 ev = ecv[c4 * 64 + cl];
            #pragma unroll
            for (int t = 0; t < 8; t++) {
                float4 zz = tz0[t * 64 + c4];
                s[t] = fmaf(zz.x, ev.x, s[t]);
                s[t] = fmaf(zz.y, ev.y, s[t]);
                s[t] = fmaf(zz.z, ev.z, s[t]);
                s[t] = fmaf(zz.w, ev.w, s[t]);
            }
        }
        __syncthreads();

        // reduce over 64 code lanes (2 warps per group), then atomic merge
        #pragma unroll
        for (int t = 0; t < 8; t++) {
            ull p = ((ull)fmap(s[t] - corr) << 13) | (ull)(8191 - k);
            #pragma unroll
            for (int x = 16; x; x >>= 1) {
                ull o = __shfl_xor_sync(0xffffffffu, p, x);
                if (o > p) p = o;
            }
            if ((tid & 31) == 0) red[(g * 8 + t) * 2 + ((tid >> 5) & 1)] = p;
        }
        __syncthreads();
        if (tid < 32) {
            int li = it * 32 + tid;
            if (li < cnt) {
                ull a = red[tid * 2], b = red[tid * 2 + 1];
                ull p = (b > a) ? b : a;
                atomicMax(&g_bestm[g_list[li]], p);
            }
        }
        __syncthreads();
    }
}

__global__ void rerank_fix() {
    int i = blockIdx.x * 256 + threadIdx.x;
    if (i < *(volatile int*)&g_nflag) {
        int n = g_list[i];
        g_idx[n] = 8191 - (int)(g_bestm[n] & 0x1FFF);
    }
}

// ---------------- output ----------------
__global__ void __launch_bounds__(256) gather_out(float* __restrict__ out) {
    __shared__ float s[32][CDIM + 1];
    __shared__ int sidx[32];
    int n0 = blockIdx.x * 32;
    if (threadIdx.x < 32) sidx[threadIdx.x] = g_idx[n0 + threadIdx.x];
    __syncthreads();
    #pragma unroll 4
    for (int i = 0; i < 32; i++) {
        int lin = threadIdx.x + i * 256;
        int t = lin >> 8, c = lin & 255;
        s[t][c] = g_en[(size_t)sidx[t] * CDIM + c];
    }
    __syncthreads();
    int b   = n0 >> 10;
    int hw0 = n0 & 1023;
    #pragma unroll 4
    for (int i = 0; i < 32; i++) {
        int lin = threadIdx.x + i * 256;
        int c = lin >> 5, t = lin & 31;
        out[((size_t)b * CDIM + c) * 1024 + hw0 + t] = s[t][c];
    }
}

__global__ void idx_out(float* __restrict__ o) {
    int n = blockIdx.x * 256 + threadIdx.x;
    o[n] = (float)g_idx[n];
}

extern "C" void kernel_launch(void* const* d_in, const int* in_sizes, int n_in,
                              void* d_out, int out_size) {
    const float* z   = (const float*)d_in[0];
    const float* emb = (const float*)d_in[1];
    float* out = (float*)d_out;

    cudaFuncSetAttribute(vq_main,     cudaFuncAttributeMaxDynamicSharedMemorySize, VQ_SMEM);
    cudaFuncSetAttribute(rerank_part, cudaFuncAttributeMaxDynamicSharedMemorySize, RR_SMEM);

    norm_codebook<<<KCB / 8, 256>>>(emb);
    norm_tokens<<<NTOK / 128, 256>>>(z);
    vq_main<<<NTOK / 128, 256, VQ_SMEM>>>();
    rerank_part<<<128, 256, RR_SMEM>>>();
    rerank_fix<<<NTOK / 256, 256>>>();
    gather_out<<<NTOK / 32, 256>>>(out);
    if (out_size >= OUT_ELEMS + NTOK)
        idx_out<<<NTOK / 256, 256>>>(out + OUT_ELEMS);
}

// round 11
// speedup vs baseline: 5.2351x; 1.0674x over previous
#include <cuda_runtime.h>
#include <cuda_fp16.h>
#include <cstdint>

typedef unsigned long long ull;

#define CDIM 256
#define KCB  8192
#define NTOK 16384
#define OUT_ELEMS (16*256*32*32)
#define MARGIN 6e-4f

#define KSPL 8                               // codebook splits
#define NCH  (128 / KSPL)                    // 64-code chunks per CTA
#define VQ_SMEM (65536 + 2*32768)            // tokens + 2 code stages
#define RR_SMEM (65536 + 32768 + 512)        // codes + 32 tokens + red

__device__ float   g_en[KCB * CDIM];         // normalized codebook fp32
__device__ float   g_corr[KCB];              // 0.5*|e_n|^2
__device__ __half2 g_e2[KCB * 128];          // half2 codebook, [k/64][c2][k%64]
__device__ float   g_zf[NTOK * CDIM];        // normalized tokens fp32 row-major
__device__ __half2 g_z2[NTOK * 128];         // half2 tokens, [n/128][c2][n%128]
__device__ ull     g_topP[KSPL * NTOK];      // per-split packed (score|invidx)
__device__ float   g_top2[KSPL * NTOK];      // per-split second-best
__device__ int     g_idx[NTOK];
__device__ int     g_nflag;
__device__ int     g_list[NTOK];
__device__ ull     g_bestm[NTOK];

// ---------------- helpers ----------------
__device__ __forceinline__ uint32_t smem_u32(const void* p) {
    uint32_t a;
    asm("{ .reg .u64 t; cvta.to.shared.u64 t, %1; cvt.u32.u64 %0, t; }" : "=r"(a) : "l"(p));
    return a;
}
#define CP16(dst, src) asm volatile("cp.async.cg.shared.global [%0], [%1], 16;" :: "r"(dst), "l"(src) : "memory")
#define CP_COMMIT()    asm volatile("cp.async.commit_group;" ::: "memory")
#define CP_WAIT1()     asm volatile("cp.async.wait_group 1;" ::: "memory")
#define CP_WAIT0()     asm volatile("cp.async.wait_group 0;" ::: "memory")

__device__ __forceinline__ unsigned fmap(float v) {
    unsigned u = __float_as_uint(v);
    return (u & 0x80000000u) ? ~u : (u | 0x80000000u);
}
__device__ __forceinline__ float funmap(unsigned u) {
    return __uint_as_float((u & 0x80000000u) ? (u ^ 0x80000000u) : ~u);
}

// ---------------- preprocessing ----------------
__global__ void norm_codebook(const float* __restrict__ emb) {
    if (blockIdx.x == 0 && threadIdx.x == 0) g_nflag = 0;
    int row  = blockIdx.x * 8 + (threadIdx.x >> 5);
    int lane = threadIdx.x & 31;
    const float4* w = (const float4*)(emb + (size_t)row * CDIM);
    float4 a = __ldg(w + lane);
    float4 b = __ldg(w + lane + 32);
    float ss = a.x*a.x + a.y*a.y + a.z*a.z + a.w*a.w
             + b.x*b.x + b.y*b.y + b.z*b.z + b.w*b.w;
    #pragma unroll
    for (int s = 16; s; s >>= 1) ss += __shfl_xor_sync(0xffffffffu, ss, s);
    float inv = 1.0f / fmaxf(sqrtf(ss), 1e-12f);
    float v[8];
    v[0]=a.x*inv; v[1]=a.y*inv; v[2]=a.z*inv; v[3]=a.w*inv;
    v[4]=b.x*inv; v[5]=b.y*inv; v[6]=b.z*inv; v[7]=b.w*inv;
    float4* o = (float4*)(g_en + (size_t)row * CDIM);
    o[lane]      = make_float4(v[0], v[1], v[2], v[3]);
    o[lane + 32] = make_float4(v[4], v[5], v[6], v[7]);
    size_t base = (size_t)(row >> 6) * 8192 + (row & 63);
    g_e2[base + (size_t)(2*lane    ) * 64] = __floats2half2_rn(v[0], v[1]);
    g_e2[base + (size_t)(2*lane + 1) * 64] = __floats2half2_rn(v[2], v[3]);
    g_e2[base + (size_t)(64 + 2*lane    ) * 64] = __floats2half2_rn(v[4], v[5]);
    g_e2[base + (size_t)(64 + 2*lane + 1) * 64] = __floats2half2_rn(v[6], v[7]);
    float ss2 = 0.f;
    #pragma unroll
    for (int j = 0; j < 8; j++) ss2 = fmaf(v[j], v[j], ss2);
    #pragma unroll
    for (int s = 16; s; s >>= 1) ss2 += __shfl_xor_sync(0xffffffffu, ss2, s);
    if (lane == 0) g_corr[row] = 0.5f * ss2;
}

__global__ void __launch_bounds__(256) norm_tokens(const float* __restrict__ z) {
    __shared__ float ssh[2][128];
    int n0 = blockIdx.x * 128;
    int b   = n0 >> 10;
    int hw0 = n0 & 1023;
    int tt = threadIdx.x & 127;
    int p  = threadIdx.x >> 7;
    const float* zp = z + ((size_t)b * CDIM + p * 128) * 1024 + hw0 + tt;

    float ss = 0.f;
    #pragma unroll 8
    for (int c = 0; c < 128; c++) { float v = zp[(size_t)c * 1024]; ss = fmaf(v, v, ss); }
    ssh[p][tt] = ss;
    __syncthreads();
    float inv = 1.0f / fmaxf(sqrtf(ssh[0][tt] + ssh[1][tt]), 1e-12f);

    int n = n0 + tt;
    float* zfout = g_zf + (size_t)n * CDIM + p * 128;
    __half2* z2out = g_z2 + (size_t)blockIdx.x * 16384 + tt;
    #pragma unroll 2
    for (int c = 0; c < 128; c += 8) {
        float v[8];
        #pragma unroll
        for (int j = 0; j < 8; j++) v[j] = zp[(size_t)(c + j) * 1024] * inv;
        *(float4*)(zfout + c)     = make_float4(v[0], v[1], v[2], v[3]);
        *(float4*)(zfout + c + 4) = make_float4(v[4], v[5], v[6], v[7]);
        #pragma unroll
        for (int q = 0; q < 4; q++) {
            int c2 = p * 64 + (c >> 1) + q;
            z2out[(size_t)c2 * 128] = __floats2half2_rn(v[2*q], v[2*q+1]);
        }
    }
}

// ---------------- main: HFMA2 partial GEMM (K-split), per-split top-2 ----------------
__global__ void __launch_bounds__(256, 1) vq_main() {
    extern __shared__ __align__(16) char smem[];
    __half2* tokS = (__half2*)smem;                       // [128 c2][128 tok]
    const uint32_t sa = smem_u32(smem);
    const int tid = threadIdx.x, tc = tid & 15, tg = tid >> 4;
    const int kspl = blockIdx.x >> 7;                     // ksplit-major for L2 reuse
    const int tile = blockIdx.x & 127;
    const int n0 = tile * 128;
    const int gc0 = kspl * NCH;

    {
        const __half2* zsrc = g_z2 + (size_t)tile * 16384;
        #pragma unroll
        for (int j = 0; j < 16; j++) { int i = tid + j*256; CP16(sa + i*16, zsrc + i*4); }
        const __half2* e0 = g_e2 + (size_t)gc0 * 8192;
        #pragma unroll
        for (int j = 0; j < 8; j++)  { int i = tid + j*256; CP16(sa + 65536 + i*16, e0 + i*4); }
        CP_COMMIT();
        #pragma unroll
        for (int j = 0; j < 8; j++)  { int i = tid + j*256; CP16(sa + 65536 + 32768 + i*16, e0 + 8192 + i*4); }
        CP_COMMIT();
    }

    float v1[8], v2[8]; int i1[8];
    #pragma unroll
    for (int t = 0; t < 8; t++) { v1[t] = -1e30f; v2[t] = -1e30f; i1[t] = 0; }

    for (int ch = 0; ch < NCH; ch++) {
        if (ch == NCH - 1) CP_WAIT0(); else CP_WAIT1();
        __syncthreads();

        const __half2* codeS = (const __half2*)(smem + 65536 + (ch & 1) * 32768);
        float facc[8][4];
        #pragma unroll
        for (int t = 0; t < 8; t++)
            #pragma unroll
            for (int j = 0; j < 4; j++) facc[t][j] = 0.f;

        #pragma unroll
        for (int seg = 0; seg < 4; seg++) {
            __half2 acc2[2][8][4];                       // parity-split chains
            const __half2 hz = __float2half2_rn(0.f);
            #pragma unroll
            for (int pp = 0; pp < 2; pp++)
                #pragma unroll
                for (int t = 0; t < 8; t++)
                    #pragma unroll
                    for (int j = 0; j < 4; j++) acc2[pp][t][j] = hz;

            #pragma unroll 4
            for (int cs = 0; cs < 32; cs++) {
                int c2 = seg * 32 + cs;
                int pp = cs & 1;
                __half2 zv[8], ev[4];
                *(uint4*)&zv[0] = *(const uint4*)(tokS + c2*128 + tg*8);
                *(uint4*)&zv[4] = *(const uint4*)(tokS + c2*128 + tg*8 + 4);
                *(uint4*)&ev[0] = *(const uint4*)(codeS + c2*64 + tc*4);
                #pragma unroll
                for (int t = 0; t < 8; t++)
                    #pragma unroll
                    for (int j = 0; j < 4; j++)
                        acc2[pp][t][j] = __hfma2(zv[t], ev[j], acc2[pp][t][j]);
            }
            #pragma unroll
            for (int t = 0; t < 8; t++)
                #pragma unroll
                for (int j = 0; j < 4; j++)
                    facc[t][j] += (__low2float(acc2[0][t][j]) + __high2float(acc2[0][t][j]))
                                + (__low2float(acc2[1][t][j]) + __high2float(acc2[1][t][j]));
        }
        __syncthreads();

        if (ch + 2 < NCH) {
            const __half2* esrc = g_e2 + (size_t)(gc0 + ch + 2) * 8192;
            uint32_t db = sa + 65536 + (ch & 1) * 32768;
            #pragma unroll
            for (int j = 0; j < 8; j++) { int i = tid + j*256; CP16(db + i*16, esrc + i*4); }
        }
        CP_COMMIT();

        int kbase = (gc0 + ch) * 64 + tc * 4;
        #pragma unroll
        for (int t = 0; t < 8; t++)
            #pragma unroll
            for (int j = 0; j < 4; j++) {
                float s = facc[t][j];
                if (s > v1[t]) { v2[t] = v1[t]; v1[t] = s; i1[t] = kbase + j; }
                else if (s > v2[t]) v2[t] = s;
            }
    }

    #pragma unroll
    for (int t = 0; t < 8; t++) {
        ull p = ((ull)fmap(v1[t]) << 13) | (ull)(8191 - i1[t]);
        float s2 = v2[t];
        #pragma unroll
        for (int x = 1; x <= 8; x <<= 1) {
            ull po = __shfl_xor_sync(0xffffffffu, p, x);
            float s2o = __shfl_xor_sync(0xffffffffu, s2, x);
            float va = funmap((unsigned)(p >> 13));
            float vb = funmap((unsigned)(po >> 13));
            s2 = fmaxf(fmaxf(s2, s2o), fminf(va, vb));
            if (po > p) p = po;
        }
        if (tc == 0) {
            int n = n0 + tg * 8 + t;
            g_topP[kspl * NTOK + n] = p;
            g_top2[kspl * NTOK + n] = s2;
        }
    }
}

// ---------------- merge K-split partials, compute margin, build list ----------------
__global__ void merge_tok() {
    int n = blockIdx.x * 256 + threadIdx.x;
    ull best = g_topP[n];
    float v1 = funmap((unsigned)(best >> 13));
    float v2 = g_top2[n];
    #pragma unroll
    for (int s = 1; s < KSPL; s++) {
        ull p = g_topP[s * NTOK + n];
        float w1 = funmap((unsigned)(p >> 13));
        float w2 = g_top2[s * NTOK + n];
        v2 = fmaxf(fmaxf(v2, w2), fminf(v1, w1));
        if (p > best) { best = p; v1 = w1; }
    }
    g_idx[n] = 8191 - (int)(best & 0x1FFF);
    if (v1 - v2 < MARGIN) {
        g_bestm[n] = 0ull;
        int pos = atomicAdd(&g_nflag, 1);
        g_list[pos] = n;
    }
}

// ---------------- rerank: 128 blocks x 64 codes, 32 tokens/iter, 8 tok/thread ----------------
__global__ void __launch_bounds__(256, 1) rerank_part() {
    int cnt = *(volatile int*)&g_nflag;
    if (cnt == 0) return;

    extern __shared__ __align__(16) char rsm[];
    float4* ecv = (float4*)rsm;                 // [64 c4][64 code]
    float4* tzv = (float4*)(rsm + 65536);       // [32 tok][64 c4]
    ull*    red = (ull*)(rsm + 65536 + 32768);  // [32 tok][2 w]

    const int tid = threadIdx.x;
    const int cl  = tid & 63;
    const int g   = tid >> 6;
    const int k0  = blockIdx.x * 64;
    const int k   = k0 + cl;
    const float corr = __ldg(&g_corr[k]);

    {
        const float4* src = (const float4*)(g_en + (size_t)k * CDIM) + g * 16;
        #pragma unroll
        for (int j = 0; j < 16; j++) {
            float4 vv = __ldg(src + j);
            ecv[(g * 16 + j) * 64 + cl] = vv;
        }
    }
    __syncthreads();

    const int witer = (cnt + 31) >> 5;
    for (int it = 0; it < witer; it++) {
        #pragma unroll
        for (int j = 0; j < 8; j++) {
            int i = tid + j * 256;
            int tok = i >> 6, c4 = i & 63;
            int li = it * 32 + tok;
            int n = g_list[(li < cnt) ? li : 0];
            tzv[tok * 64 + c4] = __ldg((const float4*)(g_zf + (size_t)n * CDIM) + c4);
        }
        __syncthreads();

        float s[8];
        #pragma unroll
        for (int t = 0; t < 8; t++) s[t] = 0.f;
        const float4* tz0 = tzv + (g * 8) * 64;
        #pragma unroll 4
        for (int c4 = 0; c4 < 64; c4++) {
            float4 ev = ecv[c4 * 64 + cl];
            #pragma unroll
            for (int t = 0; t < 8; t++) {
                float4 zz = tz0[t * 64 + c4];
                s[t] = fmaf(zz.x, ev.x, s[t]);
                s[t] = fmaf(zz.y, ev.y, s[t]);
                s[t] = fmaf(zz.z, ev.z, s[t]);
                s[t] = fmaf(zz.w, ev.w, s[t]);
            }
        }
        __syncthreads();

        #pragma unroll
        for (int t = 0; t < 8; t++) {
            ull p = ((ull)fmap(s[t] - corr) << 13) | (ull)(8191 - k);
            #pragma unroll
            for (int x = 16; x; x >>= 1) {
                ull o = __shfl_xor_sync(0xffffffffu, p, x);
                if (o > p) p = o;
            }
            if ((tid & 31) == 0) red[(g * 8 + t) * 2 + ((tid >> 5) & 1)] = p;
        }
        __syncthreads();
        if (tid < 32) {
            int li = it * 32 + tid;
            if (li < cnt) {
                ull a = red[tid * 2], b = red[tid * 2 + 1];
                ull p = (b > a) ? b : a;
                atomicMax(&g_bestm[g_list[li]], p);
            }
        }
        __syncthreads();
    }
}

__global__ void rerank_fix() {
    int i = blockIdx.x * 256 + threadIdx.x;
    if (i < *(volatile int*)&g_nflag) {
        int n = g_list[i];
        g_idx[n] = 8191 - (int)(g_bestm[n] & 0x1FFF);
    }
}

// ---------------- output ----------------
__global__ void __launch_bounds__(256) gather_out(float* __restrict__ out) {
    __shared__ float s[32][CDIM + 1];
    __shared__ int sidx[32];
    int n0 = blockIdx.x * 32;
    if (threadIdx.x < 32) sidx[threadIdx.x] = g_idx[n0 + threadIdx.x];
    __syncthreads();
    #pragma unroll 4
    for (int i = 0; i < 32; i++) {
        int lin = threadIdx.x + i * 256;
        int t = lin >> 8, c = lin & 255;
        s[t][c] = g_en[(size_t)sidx[t] * CDIM + c];
    }
    __syncthreads();
    int b   = n0 >> 10;
    int hw0 = n0 & 1023;
    #pragma unroll 4
    for (int i = 0; i < 32; i++) {
        int lin = threadIdx.x + i * 256;
        int c = lin >> 5, t = lin & 31;
        out[((size_t)b * CDIM + c) * 1024 + hw0 + t] = s[t][c];
    }
}

__global__ void idx_out(float* __restrict__ o) {
    int n = blockIdx.x * 256 + threadIdx.x;
    o[n] = (float)g_idx[n];
}

extern "C" void kernel_launch(void* const* d_in, const int* in_sizes, int n_in,
                              void* d_out, int out_size) {
    const float* z   = (const float*)d_in[0];
    const float* emb = (const float*)d_in[1];
    float* out = (float*)d_out;

    cudaFuncSetAttribute(vq_main,     cudaFuncAttributeMaxDynamicSharedMemorySize, VQ_SMEM);
    cudaFuncSetAttribute(rerank_part, cudaFuncAttributeMaxDynamicSharedMemorySize, RR_SMEM);

    norm_codebook<<<KCB / 8, 256>>>(emb);
    norm_tokens<<<NTOK / 128, 256>>>(z);
    vq_main<<<128 * KSPL, 256, VQ_SMEM>>>();
    merge_tok<<<NTOK / 256, 256>>>();
    rerank_part<<<128, 256, RR_SMEM>>>();
    rerank_fix<<<NTOK / 256, 256>>>();
    gather_out<<<NTOK / 32, 256>>>(out);
    if (out_size >= OUT_ELEMS + NTOK)
        idx_out<<<NTOK / 256, 256>>>(out + OUT_ELEMS);
}